// round 13
// baseline (speedup 1.0000x reference)
#include <cuda_runtime.h>
#include <cstdint>

// SEIR Euler, B=2^21 trajectories, 1000 steps, output = final I.
//
// Scaled state: I, eS = sdt*E, dS = c1*sdt*S.  Per-step map:
//   I' = omg*I + eS ; eS' = oms*eS + dS*I ; dS' = dS*(1 - c1*I)
// dS frozen per block => (I,eS) linear by M=[[omg,1],[dS,oms]].
// Two blocks: A=512 (M^2->M^256, applied twice; Simpson dS update with the
// free midpoint), B=488=256+128+64+32+8 (no trailing dS update).
// ~124 f32x2 ops per trajectory-pair.
//
// R10 change: 4 pairs (8 trajectories) per thread, all 24 LDG.64 front-
// batched => memory stream overlaps the long dependent compute chains,
// collapsing the wave-serialized burst/compute alternation seen in ncu
// (DRAM 41% / fma 49%, neither saturated).

#define SEIR_DT    0.01f
#define SEIR_INVN  1.0e-6f
#define PAIRS_PER_THREAD 4

#define MUL2(d, a, b) \
    asm("mul.rn.f32x2 %0, %1, %2;" : "=l"(d) : "l"(a), "l"(b))
#define ADD2(d, a, b) \
    asm("add.rn.f32x2 %0, %1, %2;" : "=l"(d) : "l"(a), "l"(b))
#define FMA2(d, a, b, c) \
    asm("fma.rn.f32x2 %0, %1, %2, %3;" : "=l"(d) : "l"(a), "l"(b), "l"(c))

// 2x2 square: [a,b;c,d]^2 = [a*a+bc, b*(a+d); c*(a+d), d*d+bc]  (6 ops)
#define SQUARE2x2(na, nb, nc, nd, a, b, c, d)  do { \
    uint64_t _t1, _t2;                                \
    MUL2(_t1, b, c);                                  \
    ADD2(_t2, a, d);                                  \
    FMA2(na, a, a, _t1);                              \
    MUL2(nb, b, _t2);                                 \
    MUL2(nc, c, _t2);                                 \
    FMA2(nd, d, d, _t1);                              \
} while (0)

// mat-vec: (x,y) <- [a,b;c,d] * (x,y)   (4 ops)
#define MATVEC2(x, y, a, b, c, d)  do { \
    uint64_t _u, _v, _xo = (x);          \
    MUL2(_u, b, y);                      \
    MUL2(_v, c, _xo);                    \
    FMA2(x, _xo, a, _u);                 \
    FMA2(y, y, d, _v);                   \
} while (0)

static __device__ __forceinline__ uint64_t pack2(float lo, float hi) {
    uint64_t r;
    asm("mov.b64 %0, {%1, %2};" : "=l"(r) : "f"(lo), "f"(hi));
    return r;
}

// Integrate one f32x2 pair for 1000 steps; returns final I (packed).
static __device__ __forceinline__ uint64_t seir_pair(
    float2 bb, float2 sg, float2 gm, float2 s0, float2 e0, float2 i0)
{
    const float k = SEIR_DT * SEIR_INVN;           // DT / N_POP
    float c1x = bb.x * k,            c1y = bb.y * k;
    float sdx = sg.x * SEIR_DT,      sdy = sg.y * SEIR_DT;
    float omgx = 1.0f - gm.x * SEIR_DT, omgy = 1.0f - gm.y * SEIR_DT; // w
    float omsx = 1.0f - sdx,            omsy = 1.0f - sdy;            // s

    uint64_t WS  = pack2(omgx + omsx, omgy + omsy);   // w + s
    uint64_t W2  = pack2(omgx * omgx, omgy * omgy);   // w^2
    uint64_t S2  = pack2(omsx * omsx, omsy * omsy);   // s^2
    uint64_t NCA  = pack2(-(512.0f/6.0f) * c1x, -(512.0f/6.0f) * c1y);
    uint64_t NCA4 = pack2(-(2048.0f/6.0f) * c1x, -(2048.0f/6.0f) * c1y);
    uint64_t NCBH = pack2(-244.0f * c1x, -244.0f * c1y);
    uint64_t ONE = pack2(1.0f, 1.0f);

    uint64_t I   = pack2(i0.x, i0.y);
    uint64_t eS  = pack2(sdx * e0.x,        sdy * e0.y);         // sdt*E0
    uint64_t dS  = pack2(c1x * sdx * s0.x,  c1y * sdy * s0.y);   // c1*sdt*S0

    // ---- Block A: 512 steps, dS frozen ----
    {
        uint64_t a2, c2, d2;
        ADD2(a2, dS, W2);          // M^2 = [[w^2+dS, w+s],[dS*(w+s), s^2+dS]]
        MUL2(c2, dS, WS);
        ADD2(d2, dS, S2);

        uint64_t a4, b4, c4, d4;
        SQUARE2x2(a4, b4, c4, d4, a2, WS, c2, d2);
        uint64_t a8, b8, c8, d8;
        SQUARE2x2(a8, b8, c8, d8, a4, b4, c4, d4);
        uint64_t a16, b16, c16, d16;
        SQUARE2x2(a16, b16, c16, d16, a8, b8, c8, d8);
        uint64_t a32, b32, c32, d32;
        SQUARE2x2(a32, b32, c32, d32, a16, b16, c16, d16);
        uint64_t a64, b64, c64, d64;
        SQUARE2x2(a64, b64, c64, d64, a32, b32, c32, d32);
        uint64_t a128, b128, c128, d128;
        SQUARE2x2(a128, b128, c128, d128, a64, b64, c64, d64);
        uint64_t a256, b256, c256, d256;
        SQUARE2x2(a256, b256, c256, d256, a128, b128, c128, d128);

        uint64_t Iold = I;
        MATVEC2(I, eS, a256, b256, c256, d256);   // -> step 256
        uint64_t Imid = I;
        MATVEC2(I, eS, a256, b256, c256, d256);   // -> step 512

        // Simpson: dS *= 1 - c1*(512/6)*(I0 + 4*Im + I1)
        uint64_t w, t, z;
        ADD2(w, Iold, I);
        FMA2(t, w, NCA, ONE);
        FMA2(z, Imid, NCA4, t);
        MUL2(dS, dS, z);
    }

    // matrix-build dS for block B, midpoint-extrapolated
    uint64_t dSb;
    {
        uint64_t z2;
        FMA2(z2, I, NCBH, ONE);
        MUL2(dSb, dS, z2);
    }

    // ---- Block B: 488 = 256+128+64+32+8 ----
    {
        uint64_t a2, c2, d2;
        ADD2(a2, dSb, W2);
        MUL2(c2, dSb, WS);
        ADD2(d2, dSb, S2);

        uint64_t a4, b4, c4, d4;
        SQUARE2x2(a4, b4, c4, d4, a2, WS, c2, d2);
        uint64_t a8, b8, c8, d8;
        SQUARE2x2(a8, b8, c8, d8, a4, b4, c4, d4);
        uint64_t a16, b16, c16, d16;
        SQUARE2x2(a16, b16, c16, d16, a8, b8, c8, d8);
        uint64_t a32, b32, c32, d32;
        SQUARE2x2(a32, b32, c32, d32, a16, b16, c16, d16);
        uint64_t a64, b64, c64, d64;
        SQUARE2x2(a64, b64, c64, d64, a32, b32, c32, d32);
        uint64_t a128, b128, c128, d128;
        SQUARE2x2(a128, b128, c128, d128, a64, b64, c64, d64);
        uint64_t a256, b256, c256, d256;
        SQUARE2x2(a256, b256, c256, d256, a128, b128, c128, d128);

        MATVEC2(I, eS, a8, b8, c8, d8);
        MATVEC2(I, eS, a32, b32, c32, d32);
        MATVEC2(I, eS, a64, b64, c64, d64);
        MATVEC2(I, eS, a128, b128, c128, d128);
        MATVEC2(I, eS, a256, b256, c256, d256);
    }

    return I;
}

__global__ void __launch_bounds__(256)
seir_mp_kernel(const float* __restrict__ beta,
               const float* __restrict__ sigma,
               const float* __restrict__ gamma,
               const float* __restrict__ S0,
               const float* __restrict__ E0,
               const float* __restrict__ I0,
               float* __restrict__ out,
               int half_n, int stride)   // stride = total threads
{
    int t = blockIdx.x * blockDim.x + threadIdx.x;

    // front-batched loads: 4 pairs x 6 inputs, all issued before compute
    float2 in_b[PAIRS_PER_THREAD], in_s[PAIRS_PER_THREAD], in_g[PAIRS_PER_THREAD];
    float2 in_S[PAIRS_PER_THREAD], in_E[PAIRS_PER_THREAD], in_I[PAIRS_PER_THREAD];

    #pragma unroll
    for (int p = 0; p < PAIRS_PER_THREAD; ++p) {
        int idx = t + p * stride;
        if (idx < half_n) {
            in_b[p] = reinterpret_cast<const float2*>(beta)[idx];
            in_s[p] = reinterpret_cast<const float2*>(sigma)[idx];
            in_g[p] = reinterpret_cast<const float2*>(gamma)[idx];
            in_S[p] = reinterpret_cast<const float2*>(S0)[idx];
            in_E[p] = reinterpret_cast<const float2*>(E0)[idx];
            in_I[p] = reinterpret_cast<const float2*>(I0)[idx];
        }
    }

    #pragma unroll
    for (int p = 0; p < PAIRS_PER_THREAD; ++p) {
        int idx = t + p * stride;
        if (idx < half_n) {
            uint64_t I = seir_pair(in_b[p], in_s[p], in_g[p],
                                   in_S[p], in_E[p], in_I[p]);
            float ix, iy;
            asm("mov.b64 {%0, %1}, %2;" : "=f"(ix), "=f"(iy) : "l"(I));
            reinterpret_cast<float2*>(out)[idx] = make_float2(ix, iy);
        }
    }
}

extern "C" void kernel_launch(void* const* d_in, const int* in_sizes, int n_in,
                              void* d_out, int out_size)
{
    // inputs: 0:beta 1:sigma 2:gamma 3:S0 4:E0 5:I0 6:R0 (unused)
    const float* beta  = (const float*)d_in[0];
    const float* sigma = (const float*)d_in[1];
    const float* gamma = (const float*)d_in[2];
    const float* S0    = (const float*)d_in[3];
    const float* E0    = (const float*)d_in[4];
    const float* I0    = (const float*)d_in[5];
    float* out = (float*)d_out;

    int n = in_sizes[0];
    int half_n = n / 2;                              // # of f32x2 pairs
    int threads = 256;
    int total_threads = (half_n + PAIRS_PER_THREAD - 1) / PAIRS_PER_THREAD;
    int blocks = (total_threads + threads - 1) / threads;
    int stride = blocks * threads;
    seir_mp_kernel<<<blocks, threads>>>(beta, sigma, gamma, S0, E0, I0,
                                        out, half_n, stride);
}

// round 14
// speedup vs baseline: 1.0216x; 1.0216x over previous
#include <cuda_runtime.h>
#include <cstdint>

// SEIR Euler, B=2^21 trajectories, 1000 steps, output = final I.
//
// Math (unchanged from R9's verified kernel): scaled state I, eS=sdt*E,
// dS=c1*sdt*S; dS frozen per block => (I,eS) linear by M=[[omg,1],[dS,oms]].
// Block A=512 (7 squarings, M^256 applied twice, Simpson dS update),
// Block B=488=256+128+64+32+8. ~124 f32x2 ops per trajectory-pair.
//
// R14 change: persistent occupancy-matched grid with per-iteration register
// prefetch (load pair i+1's inputs, compute pair i) so the DRAM stream runs
// CONCURRENTLY with the 294-cycle dependent compute chain, instead of the
// serial load-phase/compute-phase pattern measured in R9/R13.

#define SEIR_DT    0.01f
#define SEIR_INVN  1.0e-6f
#define PERSIST_CTAS 592   // ~4 CTAs/SM x 148 SMs

#define MUL2(d, a, b) \
    asm("mul.rn.f32x2 %0, %1, %2;" : "=l"(d) : "l"(a), "l"(b))
#define ADD2(d, a, b) \
    asm("add.rn.f32x2 %0, %1, %2;" : "=l"(d) : "l"(a), "l"(b))
#define FMA2(d, a, b, c) \
    asm("fma.rn.f32x2 %0, %1, %2, %3;" : "=l"(d) : "l"(a), "l"(b), "l"(c))

// 2x2 square: [a,b;c,d]^2 = [a*a+bc, b*(a+d); c*(a+d), d*d+bc]  (6 ops)
#define SQUARE2x2(na, nb, nc, nd, a, b, c, d)  do { \
    uint64_t _t1, _t2;                                \
    MUL2(_t1, b, c);                                  \
    ADD2(_t2, a, d);                                  \
    FMA2(na, a, a, _t1);                              \
    MUL2(nb, b, _t2);                                 \
    MUL2(nc, c, _t2);                                 \
    FMA2(nd, d, d, _t1);                              \
} while (0)

// mat-vec: (x,y) <- [a,b;c,d] * (x,y)   (4 ops)
#define MATVEC2(x, y, a, b, c, d)  do { \
    uint64_t _u, _v, _xo = (x);          \
    MUL2(_u, b, y);                      \
    MUL2(_v, c, _xo);                    \
    FMA2(x, _xo, a, _u);                 \
    FMA2(y, y, d, _v);                   \
} while (0)

static __device__ __forceinline__ uint64_t pack2(float lo, float hi) {
    uint64_t r;
    asm("mov.b64 %0, {%1, %2};" : "=l"(r) : "f"(lo), "f"(hi));
    return r;
}

// Integrate one f32x2 pair (2 trajectories) for 1000 steps; returns final I.
static __device__ __forceinline__ uint64_t seir_pair(
    float2 bb, float2 sg, float2 gm, float2 s0, float2 e0, float2 i0)
{
    const float k = SEIR_DT * SEIR_INVN;           // DT / N_POP
    float c1x = bb.x * k,            c1y = bb.y * k;
    float sdx = sg.x * SEIR_DT,      sdy = sg.y * SEIR_DT;
    float omgx = 1.0f - gm.x * SEIR_DT, omgy = 1.0f - gm.y * SEIR_DT; // w
    float omsx = 1.0f - sdx,            omsy = 1.0f - sdy;            // s

    uint64_t WS  = pack2(omgx + omsx, omgy + omsy);   // w + s
    uint64_t W2  = pack2(omgx * omgx, omgy * omgy);   // w^2
    uint64_t S2  = pack2(omsx * omsx, omsy * omsy);   // s^2
    uint64_t NCA  = pack2(-(512.0f/6.0f) * c1x, -(512.0f/6.0f) * c1y);
    uint64_t NCA4 = pack2(-(2048.0f/6.0f) * c1x, -(2048.0f/6.0f) * c1y);
    uint64_t NCBH = pack2(-244.0f * c1x, -244.0f * c1y);
    uint64_t ONE = pack2(1.0f, 1.0f);

    uint64_t I   = pack2(i0.x, i0.y);
    uint64_t eS  = pack2(sdx * e0.x,        sdy * e0.y);         // sdt*E0
    uint64_t dS  = pack2(c1x * sdx * s0.x,  c1y * sdy * s0.y);   // c1*sdt*S0

    // ---- Block A: 512 steps, dS frozen ----
    {
        uint64_t a2, c2, d2;
        ADD2(a2, dS, W2);          // M^2 = [[w^2+dS, w+s],[dS*(w+s), s^2+dS]]
        MUL2(c2, dS, WS);
        ADD2(d2, dS, S2);

        uint64_t a4, b4, c4, d4;
        SQUARE2x2(a4, b4, c4, d4, a2, WS, c2, d2);
        uint64_t a8, b8, c8, d8;
        SQUARE2x2(a8, b8, c8, d8, a4, b4, c4, d4);
        uint64_t a16, b16, c16, d16;
        SQUARE2x2(a16, b16, c16, d16, a8, b8, c8, d8);
        uint64_t a32, b32, c32, d32;
        SQUARE2x2(a32, b32, c32, d32, a16, b16, c16, d16);
        uint64_t a64, b64, c64, d64;
        SQUARE2x2(a64, b64, c64, d64, a32, b32, c32, d32);
        uint64_t a128, b128, c128, d128;
        SQUARE2x2(a128, b128, c128, d128, a64, b64, c64, d64);
        uint64_t a256, b256, c256, d256;
        SQUARE2x2(a256, b256, c256, d256, a128, b128, c128, d128);

        uint64_t Iold = I;
        MATVEC2(I, eS, a256, b256, c256, d256);   // -> step 256
        uint64_t Imid = I;
        MATVEC2(I, eS, a256, b256, c256, d256);   // -> step 512

        // Simpson: dS *= 1 - c1*(512/6)*(I0 + 4*Im + I1)
        uint64_t w, t, z;
        ADD2(w, Iold, I);
        FMA2(t, w, NCA, ONE);
        FMA2(z, Imid, NCA4, t);
        MUL2(dS, dS, z);
    }

    // matrix-build dS for block B, midpoint-extrapolated
    uint64_t dSb;
    {
        uint64_t z2;
        FMA2(z2, I, NCBH, ONE);
        MUL2(dSb, dS, z2);
    }

    // ---- Block B: 488 = 256+128+64+32+8 ----
    {
        uint64_t a2, c2, d2;
        ADD2(a2, dSb, W2);
        MUL2(c2, dSb, WS);
        ADD2(d2, dSb, S2);

        uint64_t a4, b4, c4, d4;
        SQUARE2x2(a4, b4, c4, d4, a2, WS, c2, d2);
        uint64_t a8, b8, c8, d8;
        SQUARE2x2(a8, b8, c8, d8, a4, b4, c4, d4);
        uint64_t a16, b16, c16, d16;
        SQUARE2x2(a16, b16, c16, d16, a8, b8, c8, d8);
        uint64_t a32, b32, c32, d32;
        SQUARE2x2(a32, b32, c32, d32, a16, b16, c16, d16);
        uint64_t a64, b64, c64, d64;
        SQUARE2x2(a64, b64, c64, d64, a32, b32, c32, d32);
        uint64_t a128, b128, c128, d128;
        SQUARE2x2(a128, b128, c128, d128, a64, b64, c64, d64);
        uint64_t a256, b256, c256, d256;
        SQUARE2x2(a256, b256, c256, d256, a128, b128, c128, d128);

        MATVEC2(I, eS, a8, b8, c8, d8);
        MATVEC2(I, eS, a32, b32, c32, d32);
        MATVEC2(I, eS, a64, b64, c64, d64);
        MATVEC2(I, eS, a128, b128, c128, d128);
        MATVEC2(I, eS, a256, b256, c256, d256);
    }

    return I;
}

__global__ void __launch_bounds__(256)
seir_persist_kernel(const float* __restrict__ beta,
                    const float* __restrict__ sigma,
                    const float* __restrict__ gamma,
                    const float* __restrict__ S0,
                    const float* __restrict__ E0,
                    const float* __restrict__ I0,
                    float* __restrict__ out,
                    int half_n)
{
    const int T = gridDim.x * blockDim.x;           // total threads (stride)
    int idx = blockIdx.x * blockDim.x + threadIdx.x;
    if (idx >= half_n) return;

    // prologue: load first pair
    float2 cb = reinterpret_cast<const float2*>(beta)[idx];
    float2 cs = reinterpret_cast<const float2*>(sigma)[idx];
    float2 cg = reinterpret_cast<const float2*>(gamma)[idx];
    float2 cS = reinterpret_cast<const float2*>(S0)[idx];
    float2 cE = reinterpret_cast<const float2*>(E0)[idx];
    float2 cI = reinterpret_cast<const float2*>(I0)[idx];

    while (true) {
        int nidx = idx + T;
        // prefetch next pair's inputs (independent of current compute;
        // ptxas hoists these LDGs above the dependent FMA chain)
        float2 nb, ns, ng, nS, nE, nI;
        bool have_next = (nidx < half_n);
        if (have_next) {
            nb = reinterpret_cast<const float2*>(beta)[nidx];
            ns = reinterpret_cast<const float2*>(sigma)[nidx];
            ng = reinterpret_cast<const float2*>(gamma)[nidx];
            nS = reinterpret_cast<const float2*>(S0)[nidx];
            nE = reinterpret_cast<const float2*>(E0)[nidx];
            nI = reinterpret_cast<const float2*>(I0)[nidx];
        }

        // long dependent compute on current pair (~294 pipe cycles)
        uint64_t I = seir_pair(cb, cs, cg, cS, cE, cI);
        float ix, iy;
        asm("mov.b64 {%0, %1}, %2;" : "=f"(ix), "=f"(iy) : "l"(I));
        reinterpret_cast<float2*>(out)[idx] = make_float2(ix, iy);

        if (!have_next) break;
        idx = nidx;
        cb = nb; cs = ns; cg = ng; cS = nS; cE = nE; cI = nI;
    }
}

extern "C" void kernel_launch(void* const* d_in, const int* in_sizes, int n_in,
                              void* d_out, int out_size)
{
    // inputs: 0:beta 1:sigma 2:gamma 3:S0 4:E0 5:I0 6:R0 (unused)
    const float* beta  = (const float*)d_in[0];
    const float* sigma = (const float*)d_in[1];
    const float* gamma = (const float*)d_in[2];
    const float* S0    = (const float*)d_in[3];
    const float* E0    = (const float*)d_in[4];
    const float* I0    = (const float*)d_in[5];
    float* out = (float*)d_out;

    int n = in_sizes[0];
    int half_n = n / 2;   // number of f32x2 pairs (B even)
    seir_persist_kernel<<<PERSIST_CTAS, 256>>>(beta, sigma, gamma,
                                               S0, E0, I0, out, half_n);
}